// round 5
// baseline (speedup 1.0000x reference)
#include <cuda_runtime.h>
#include <cuda_bf16.h>

// Problem: B=128, O=1024, I=1024
//   c[o,i]      = (ix/iy + la)*(1+lm) - ox/oy            (batch independent)
//   s[b,o,i]    = rsqrt(c^2 * sigmoid(d[b,i])^2 + eps)
//   w           = softmax over o of s
//   out[b,o]    = sum_i d[b,i] * w[b,o,i]
//
// Pipeline:
//   1) init_min: reset per-i running min (graph-replay safe)
//   2) prep: c^2 transposed to [i][o] + cmin2[i] = min_o c^2   (gives softmax max analytically)
//   3) main: one warp owns a full o-column for (b, i); computes e_o = exp(s-m) ONCE,
//      warp-reduces Z, accumulates (d/Z)*e_o into 32 per-lane registers over an i-chunk.
//   4) reduce: sum per-chunk partials into d_out.

#define BB 128
#define OO 1024
#define NI 1024
#define NCHUNK 32
#define ICH (NI / NCHUNK)   // 32 i per warp-unit
#define BW 4                // warps (= batches) per block
#define EPSV 1e-7f
#define L2E 1.4426950408889634f

__device__ float g_c2T[NI * OO];                 // c^2, [i][o] layout (4 MB)
__device__ unsigned int g_cmin[NI];              // min_o c^2 per i (uint bits of nonneg float)
__device__ float g_part[NCHUNK * BB * OO];       // per-chunk output partials (16 MB)

__global__ void init_min_kernel() {
    g_cmin[threadIdx.x] = 0x7F800000u;           // +inf
}

__global__ __launch_bounds__(256) void prep_kernel(
    const float* __restrict__ ix, const float* __restrict__ iy,
    const float* __restrict__ ox, const float* __restrict__ oy,
    const float* __restrict__ la, const float* __restrict__ lm)
{
    __shared__ float tile[32][33];
    const int i0 = blockIdx.x * 32;
    const int o0 = blockIdx.y * 32;
    const int tx = threadIdx.x;                  // 0..31 -> i within tile (read), o within tile (write)
    const int ty = threadIdx.y;                  // 0..7

#pragma unroll
    for (int r = 0; r < 4; ++r) {
        const int ol = ty + r * 8;
        const int idx = (o0 + ol) * NI + i0 + tx;
        const float inp = ix[idx] / iy[idx];     // IEEE div: c is cancellation-sensitive
        const float ou  = ox[idx] / oy[idx];
        const float c   = (inp + la[idx]) * (1.0f + lm[idx]) - ou;
        tile[ol][tx] = c * c;                    // tile[o_local][i_local]
    }
    __syncthreads();

#pragma unroll
    for (int r = 0; r < 4; ++r) {
        const int il = ty + r * 8;
        g_c2T[(i0 + il) * OO + o0 + tx] = tile[tx][il];   // coalesced in o
    }

    if (ty == 0) {                               // warp 0: per-i min over this block's 32 o's
        float mn = tile[0][tx];
#pragma unroll
        for (int o = 1; o < 32; ++o) mn = fminf(mn, tile[o][tx]);
        atomicMin(&g_cmin[i0 + tx], __float_as_uint(mn));  // nonneg floats: uint order == float order
    }
}

__global__ __launch_bounds__(128, 4) void main_kernel(const float* __restrict__ dptr) {
    const int lane  = threadIdx.x & 31;
    const int warp  = threadIdx.x >> 5;
    const int b     = blockIdx.x * BW + warp;    // one batch per warp
    const int chunk = blockIdx.y;
    const int i0    = chunk * ICH;

    float acc[32];
#pragma unroll
    for (int t = 0; t < 32; ++t) acc[t] = 0.0f;

    const float4* c2 = reinterpret_cast<const float4*>(g_c2T);

    for (int ii = 0; ii < ICH; ++ii) {
        const int i = i0 + ii;
        const float dv = __ldg(dptr + b * NI + i);

        // sigmoid(dv)^2
        float ex_;
        asm("ex2.approx.ftz.f32 %0, %1;" : "=f"(ex_) : "f"(-dv * L2E));
        const float sig  = __fdividef(1.0f, 1.0f + ex_);
        const float sig2 = sig * sig;

        // softmax max from precomputed min_o c^2 (rsqrt monotone decreasing)
        const float cm = __uint_as_float(g_cmin[i]);
        float m_;
        {
            const float xm = fmaf(cm, sig2, EPSV);
            asm("rsqrt.approx.ftz.f32 %0, %1;" : "=f"(m_) : "f"(xm));
        }
        const float nmL = -(m_ * L2E);

        float e[32];
        float p0 = 0.0f, p1 = 0.0f, p2 = 0.0f, p3 = 0.0f;
        const float4* row = c2 + i * (OO / 4) + lane;

#pragma unroll
        for (int k = 0; k < 8; ++k) {
            const float4 v = __ldg(row + k * 32);   // o = 128*k + 4*lane + j, coalesced 128B
#define AEG_DO(comp, slot, pacc) {                                              \
            float x_ = fmaf(comp, sig2, EPSV);                                  \
            float s_; asm("rsqrt.approx.ftz.f32 %0, %1;" : "=f"(s_) : "f"(x_)); \
            float a_ = fmaf(s_, L2E, nmL);                                      \
            float e_; asm("ex2.approx.ftz.f32 %0, %1;" : "=f"(e_) : "f"(a_));   \
            e[slot] = e_; pacc += e_; }
            AEG_DO(v.x, k * 4 + 0, p0)
            AEG_DO(v.y, k * 4 + 1, p1)
            AEG_DO(v.z, k * 4 + 2, p2)
            AEG_DO(v.w, k * 4 + 3, p3)
#undef AEG_DO
        }

        float ps = (p0 + p1) + (p2 + p3);        // Z partial, 32 terms per lane
#pragma unroll
        for (int off = 16; off > 0; off >>= 1)
            ps += __shfl_xor_sync(0xffffffffu, ps, off);

        const float gz = __fdividef(dv, ps);     // ps >= 1 (max term == 1), safe
#pragma unroll
        for (int t = 0; t < 32; ++t) acc[t] = fmaf(gz, e[t], acc[t]);
    }

    // write per-chunk partials (no atomics): part[chunk][b][o]
    float4* part = reinterpret_cast<float4*>(g_part) + (chunk * BB + b) * (OO / 4);
#pragma unroll
    for (int k = 0; k < 8; ++k)
        part[k * 32 + lane] =
            make_float4(acc[k * 4 + 0], acc[k * 4 + 1], acc[k * 4 + 2], acc[k * 4 + 3]);
}

__global__ __launch_bounds__(256) void reduce_kernel(float* __restrict__ out) {
    const int idx = blockIdx.x * 256 + threadIdx.x;   // idx = b*OO + o, grid covers B*O exactly
    float s = 0.0f;
#pragma unroll
    for (int c = 0; c < NCHUNK; ++c) s += g_part[c * BB * OO + idx];
    out[idx] = s;
}

extern "C" void kernel_launch(void* const* d_in, const int* in_sizes, int n_in,
                              void* d_out, int out_size) {
    (void)in_sizes; (void)n_in; (void)out_size;
    const float* data = (const float*)d_in[0];
    const float* ix   = (const float*)d_in[1];
    const float* iy   = (const float*)d_in[2];
    const float* ox   = (const float*)d_in[3];
    const float* oy   = (const float*)d_in[4];
    const float* la   = (const float*)d_in[5];
    const float* lm   = (const float*)d_in[6];
    float* out = (float*)d_out;

    init_min_kernel<<<1, NI>>>();
    prep_kernel<<<dim3(NI / 32, OO / 32), dim3(32, 8)>>>(ix, iy, ox, oy, la, lm);
    main_kernel<<<dim3(BB / BW, NCHUNK), 128>>>(data);
    reduce_kernel<<<(BB * OO) / 256, 256>>>(out);
}

// round 6
// speedup vs baseline: 1.2139x; 1.2139x over previous
#include <cuda_runtime.h>
#include <cuda_bf16.h>
#include <math_constants.h>

// Problem: B=128, O=1024, I=1024
//   c[o,i]   = (ix/iy + la)*(1+lm) - ox/oy               (batch independent)
//   s[b,o,i] = rsqrt(c^2 * sigmoid(d[b,i])^2 + eps)
//   w        = softmax over o of s
//   out[b,o] = sum_i d[b,i] * w[b,o,i]
//
// Round 5: exploit that the softmax is a near-argmin selector. Terms with
// s < m - 25 contribute < e^-25 each (<1e-8 total, Z>=1) and are skipped via a
// threshold on c^2 (warp-uniform branch per float4 group) — this removes both
// MUFU ops (RSQ, EX2) for ~97% of elements. T > cmin always, so the max term
// (which pins Z >= 1) is never dropped. NCHUNK halved to shrink partials.

#define BB 128
#define OO 1024
#define NI 1024
#define NCHUNK 16
#define ICH (NI / NCHUNK)   // 64 i per warp-unit
#define BW 4                // warps (= batches) per block
#define EPSV 1e-7f
#define L2E 1.4426950408889634f
#define SKIP_MARGIN 25.0f   // drop terms with s < m - 25  (each < e^-25)

__device__ float g_c2T[NI * OO];                 // c^2, [i][o] layout (4 MB)
__device__ unsigned int g_cmin[NI];              // min_o c^2 per i (uint bits of nonneg float)
__device__ float g_part[NCHUNK * BB * OO];       // per-chunk output partials (8 MB)

__global__ void init_min_kernel() {
    g_cmin[threadIdx.x] = 0x7F800000u;           // +inf
}

__global__ __launch_bounds__(256) void prep_kernel(
    const float* __restrict__ ix, const float* __restrict__ iy,
    const float* __restrict__ ox, const float* __restrict__ oy,
    const float* __restrict__ la, const float* __restrict__ lm)
{
    __shared__ float tile[32][33];
    const int i0 = blockIdx.x * 32;
    const int o0 = blockIdx.y * 32;
    const int tx = threadIdx.x;
    const int ty = threadIdx.y;

#pragma unroll
    for (int r = 0; r < 4; ++r) {
        const int ol = ty + r * 8;
        const int idx = (o0 + ol) * NI + i0 + tx;
        const float inp = ix[idx] / iy[idx];     // IEEE div: c is cancellation-sensitive
        const float ou  = ox[idx] / oy[idx];
        const float c   = (inp + la[idx]) * (1.0f + lm[idx]) - ou;
        tile[ol][tx] = c * c;
    }
    __syncthreads();

#pragma unroll
    for (int r = 0; r < 4; ++r) {
        const int il = ty + r * 8;
        g_c2T[(i0 + il) * OO + o0 + tx] = tile[tx][il];   // coalesced in o
    }

    if (ty == 0) {
        float mn = tile[0][tx];
#pragma unroll
        for (int o = 1; o < 32; ++o) mn = fminf(mn, tile[o][tx]);
        atomicMin(&g_cmin[i0 + tx], __float_as_uint(mn));  // nonneg: uint order == float order
    }
}

__global__ __launch_bounds__(128, 4) void main_kernel(const float* __restrict__ dptr) {
    const int lane  = threadIdx.x & 31;
    const int warp  = threadIdx.x >> 5;
    const int b     = blockIdx.x * BW + warp;    // one batch per warp
    const int chunk = blockIdx.y;
    const int i0    = chunk * ICH;

    float acc[32];
#pragma unroll
    for (int t = 0; t < 32; ++t) acc[t] = 0.0f;

    const float4* c2 = reinterpret_cast<const float4*>(g_c2T);

    for (int ii = 0; ii < ICH; ++ii) {
        const int i = i0 + ii;
        const float dv = __ldg(dptr + b * NI + i);

        // sigmoid(dv)^2
        float ex_;
        asm("ex2.approx.ftz.f32 %0, %1;" : "=f"(ex_) : "f"(-dv * L2E));
        const float sig  = __fdividef(1.0f, 1.0f + ex_);
        const float sig2 = sig * sig;

        // softmax max from precomputed min_o c^2 (rsqrt monotone decreasing)
        const float cm = __uint_as_float(g_cmin[i]);
        float m_;
        {
            const float xm = fmaf(cm, sig2, EPSV);
            asm("rsqrt.approx.ftz.f32 %0, %1;" : "=f"(m_) : "f"(xm));
        }
        const float nmL = -(m_ * L2E);

        // c^2 skip threshold: s >= m-25  <=>  c^2 <= T.
        // t = 1/(m-25) > 1/m  =>  t^2 > cm*sig2+eps  =>  T > cm >= 0 (argmin never dropped).
        float T;
        if (m_ > SKIP_MARGIN + 2.0f) {
            const float t = __fdividef(1.0f, m_ - SKIP_MARGIN);
            T = (fmaf(t, t, -EPSV)) * __fdividef(1.0f, sig2);
        } else {
            T = CUDART_INF_F;                    // weak peaking: compute everything
        }

        float e[32];
        float p0 = 0.0f, p1 = 0.0f, p2 = 0.0f, p3 = 0.0f;
        unsigned skipmask = 0;
        const float4* row = c2 + i * (OO / 4) + lane;

#pragma unroll
        for (int k = 0; k < 8; ++k) {
            const float4 v = __ldg(row + k * 32);   // o = 128*k + 4*lane + j, coalesced 128B
            const float mn = fminf(fminf(v.x, v.y), fminf(v.z, v.w));
            if (__any_sync(0xffffffffu, mn <= T)) {
#define AEG_DO(comp, slot, pacc) {                                              \
                float x_ = fmaf(comp, sig2, EPSV);                              \
                float s_; asm("rsqrt.approx.ftz.f32 %0, %1;" : "=f"(s_) : "f"(x_)); \
                float a_ = fmaf(s_, L2E, nmL);                                  \
                float e_; asm("ex2.approx.ftz.f32 %0, %1;" : "=f"(e_) : "f"(a_)); \
                e[slot] = e_; pacc += e_; }
                AEG_DO(v.x, k * 4 + 0, p0)
                AEG_DO(v.y, k * 4 + 1, p1)
                AEG_DO(v.z, k * 4 + 2, p2)
                AEG_DO(v.w, k * 4 + 3, p3)
#undef AEG_DO
            } else {
                skipmask |= (1u << k);           // all 128 elems in group < e^-25: drop
            }
        }

        float ps = (p0 + p1) + (p2 + p3);        // Z partial
#pragma unroll
        for (int off = 16; off > 0; off >>= 1)
            ps += __shfl_xor_sync(0xffffffffu, ps, off);

        const float gz = __fdividef(dv, ps);     // max term e==1 always kept => ps >= ~1
#pragma unroll
        for (int k = 0; k < 8; ++k) {
            if (!(skipmask & (1u << k))) {
#pragma unroll
                for (int j = 0; j < 4; ++j)
                    acc[k * 4 + j] = fmaf(gz, e[k * 4 + j], acc[k * 4 + j]);
            }
        }
    }

    // write per-chunk partials (no atomics): part[chunk][b][o]
    float4* part = reinterpret_cast<float4*>(g_part) + (chunk * BB + b) * (OO / 4);
#pragma unroll
    for (int k = 0; k < 8; ++k)
        part[k * 32 + lane] =
            make_float4(acc[k * 4 + 0], acc[k * 4 + 1], acc[k * 4 + 2], acc[k * 4 + 3]);
}

__global__ __launch_bounds__(256) void reduce_kernel(float* __restrict__ out) {
    const int idx = blockIdx.x * 256 + threadIdx.x;   // idx = b*OO + o
    float s = 0.0f;
#pragma unroll
    for (int c = 0; c < NCHUNK; ++c) s += g_part[c * BB * OO + idx];
    out[idx] = s;
}

extern "C" void kernel_launch(void* const* d_in, const int* in_sizes, int n_in,
                              void* d_out, int out_size) {
    (void)in_sizes; (void)n_in; (void)out_size;
    const float* data = (const float*)d_in[0];
    const float* ix   = (const float*)d_in[1];
    const float* iy   = (const float*)d_in[2];
    const float* ox   = (const float*)d_in[3];
    const float* oy   = (const float*)d_in[4];
    const float* la   = (const float*)d_in[5];
    const float* lm   = (const float*)d_in[6];
    float* out = (float*)d_out;

    init_min_kernel<<<1, NI>>>();
    prep_kernel<<<dim3(NI / 32, OO / 32), dim3(32, 8)>>>(ix, iy, ox, oy, la, lm);
    main_kernel<<<dim3(BB / BW, NCHUNK), 128>>>(data);
    reduce_kernel<<<(BB * OO) / 256, 256>>>(out);
}

// round 7
// speedup vs baseline: 1.5365x; 1.2658x over previous
#include <cuda_runtime.h>
#include <cuda_bf16.h>
#include <math_constants.h>

// Problem: B=128, O=1024, I=1024
//   c[o,i]   = (ix/iy + la)*(1+lm) - ox/oy               (batch independent)
//   s[b,o,i] = rsqrt(c^2 * sigmoid(d[b,i])^2 + eps)
//   w        = softmax over o of s ; out[b,o] = sum_i d[b,i]*w
//
// R6: the softmax survivor set {o : c^2 <= T(b,i)} is always the few smallest
// c^2 in row i. Precompute per-i candidate lists (c^2 <= Trow[i] where Trow
// bounds T over all b), plus a per-(b,i) table {dv, sig2, -m*log2e, T_b}.
// Main: one candidate load + 1 RSQ + 1 EX2 per warp per (b,i), warp-reduce Z,
// scatter ~2 atomicAdds into out. Exact check T_b <= Trow falls back to the
// full-row path, so the Trow bound is never correctness-critical.

#define BB 128
#define OO 1024
#define NI 1024
#define NCHUNK 32
#define ICH (NI / NCHUNK)   // 32 i per warp-unit
#define BW 4                // warps (= batches) per block
#define EPSV 1e-7f
#define L2E 1.4426950408889634f
#define MAXCAND 32

__device__ float        g_c2T[NI * OO];          // c^2, [i][o] layout (4 MB) — slow path + cand scan
__device__ unsigned int g_cmin[NI];              // min_o c^2 per i (uint bits of nonneg float)
__device__ float        g_trow[NI];              // per-row candidate threshold
__device__ int          g_ncand[NI];             // candidate count (or OO+1 sentinel)
__device__ float        g_candv[NI * MAXCAND];   // candidate c^2, +inf padded
__device__ int          g_cando[NI * MAXCAND];   // candidate original o
__device__ float4       g_tab[BB * NI];          // {dv, sig2, nmL, T_b} per (b,i)

__global__ __launch_bounds__(1024) void init_kernel(float* __restrict__ out) {
    const int idx = blockIdx.x * 1024 + threadIdx.x;
    out[idx] = 0.0f;                             // atomics accumulate into out
    if (blockIdx.x == 0) g_cmin[threadIdx.x] = 0x7F800000u;  // +inf
}

__global__ __launch_bounds__(256) void prep_kernel(
    const float* __restrict__ ix, const float* __restrict__ iy,
    const float* __restrict__ ox, const float* __restrict__ oy,
    const float* __restrict__ la, const float* __restrict__ lm)
{
    __shared__ float tile[32][33];
    const int i0 = blockIdx.x * 32;
    const int o0 = blockIdx.y * 32;
    const int tx = threadIdx.x;
    const int ty = threadIdx.y;

#pragma unroll
    for (int r = 0; r < 4; ++r) {
        const int ol = ty + r * 8;
        const int idx = (o0 + ol) * NI + i0 + tx;
        const float inp = ix[idx] / iy[idx];     // IEEE div: c is cancellation-sensitive
        const float ou  = ox[idx] / oy[idx];
        const float c   = (inp + la[idx]) * (1.0f + lm[idx]) - ou;
        tile[ol][tx] = c * c;
    }
    __syncthreads();

#pragma unroll
    for (int r = 0; r < 4; ++r) {
        const int il = ty + r * 8;
        g_c2T[(i0 + il) * OO + o0 + tx] = tile[tx][il];   // coalesced in o
    }

    if (ty == 0) {
        float mn = tile[0][tx];
#pragma unroll
        for (int o = 1; o < 32; ++o) mn = fminf(mn, tile[o][tx]);
        atomicMin(&g_cmin[i0 + tx], __float_as_uint(mn));  // nonneg: uint order == float order
    }
}

// One block per i: compute Trow, compact candidates (c^2 <= Trow).
__global__ __launch_bounds__(256) void cand_kernel() {
    const int i = blockIdx.x;
    __shared__ int cnt;
    if (threadIdx.x == 0) cnt = 0;
    __syncthreads();

    const float cm = __uint_as_float(g_cmin[i]);
    float m1;                                    // smallest possible softmax max (sig2 = 1)
    asm("rsqrt.approx.ftz.f32 %0, %1;" : "=f"(m1) : "f"(cm + EPSV));
    float trow;
    if (m1 > 28.0f) {
        const float t = __fdividef(1.0f, m1 - 26.0f);          // margin 26 vs T_b's 25
        trow = fmaf(t, t, 0.02f * EPSV * 1e4f);                // + eps-term cover for sig2 >= 1e-4
    } else {
        trow = CUDART_INF_F;                     // weakly peaked row: everything slow-path
    }
    if (threadIdx.x == 0) g_trow[i] = trow;

    for (int o = threadIdx.x; o < OO; o += 256) {
        const float c2 = g_c2T[i * OO + o];
        if (c2 <= trow) {
            const int p = atomicAdd(&cnt, 1);
            if (p < MAXCAND) { g_candv[i * MAXCAND + p] = c2; g_cando[i * MAXCAND + p] = o; }
        }
    }
    __syncthreads();

    const int n = cnt;
    if (threadIdx.x == 0) g_ncand[i] = (n > MAXCAND) ? (OO + 1) : n;
    for (int p = n + threadIdx.x; p < MAXCAND; p += 256) {
        g_candv[i * MAXCAND + p] = CUDART_INF_F;               // inf -> rsqrt=0 -> e ~ 2^-39
        g_cando[i * MAXCAND + p] = 0;
    }
}

// Per-(b,i) table: dv, sig2, nmL = -m*log2e, exact skip threshold T_b.
__global__ __launch_bounds__(256) void tab_kernel(const float* __restrict__ dptr) {
    const int idx = blockIdx.x * 256 + threadIdx.x;            // idx = b*NI + i
    const int i = idx & (NI - 1);
    const float dv = dptr[idx];

    float ex_;
    asm("ex2.approx.ftz.f32 %0, %1;" : "=f"(ex_) : "f"(-dv * L2E));
    const float sig  = __fdividef(1.0f, 1.0f + ex_);
    const float sig2 = sig * sig;

    const float cm = __uint_as_float(g_cmin[i]);
    float m_;
    asm("rsqrt.approx.ftz.f32 %0, %1;" : "=f"(m_) : "f"(fmaf(cm, sig2, EPSV)));
    const float nmL = -(m_ * L2E);

    float T;
    if (m_ > 27.0f) {                            // s >= m-25  <=>  c^2 <= T
        const float t = __fdividef(1.0f, m_ - 25.0f);
        T = fmaf(t, t, -EPSV) * __fdividef(1.0f, sig2);
    } else {
        T = CUDART_INF_F;
    }
    g_tab[idx] = make_float4(dv, sig2, nmL, T);
}

__global__ __launch_bounds__(128, 8) void main_kernel(float* __restrict__ out) {
    const int lane  = threadIdx.x & 31;
    const int warp  = threadIdx.x >> 5;
    const int b     = blockIdx.x * BW + warp;    // one batch per warp
    const int i0    = blockIdx.y * ICH;

    const float4* c2 = reinterpret_cast<const float4*>(g_c2T);
    float* const outb = out + b * OO;

    for (int ii = 0; ii < ICH; ++ii) {
        const int i = i0 + ii;
        const float4 tb = g_tab[b * NI + i];     // {dv, sig2, nmL, T_b} uniform LDG.128
        const float trow = g_trow[i];
        const int   n    = g_ncand[i];

        if (tb.w <= trow && n <= MAXCAND) {
            // ---- fast path: candidates cover all terms with s >= m-25 ----
            const float c2v = g_candv[i * MAXCAND + lane];
            const int   oo  = g_cando[i * MAXCAND + lane];
            float s_, e_;
            asm("rsqrt.approx.ftz.f32 %0, %1;" : "=f"(s_) : "f"(fmaf(c2v, tb.y, EPSV)));
            asm("ex2.approx.ftz.f32 %0, %1;"   : "=f"(e_) : "f"(fmaf(s_, L2E, tb.z)));
            float ps = e_;                       // Z: argmin lane has e == 1 exactly
#pragma unroll
            for (int off = 16; off > 0; off >>= 1)
                ps += __shfl_xor_sync(0xffffffffu, ps, off);
            const float val = __fdividef(tb.x, ps) * e_;
            if (lane < n && fabsf(val) > 1e-18f)
                atomicAdd(outb + oo, val);
        } else {
            // ---- slow path: full row with group skip (rare) ----
            float e[32];
            float p0 = 0.0f, p1 = 0.0f, p2 = 0.0f, p3 = 0.0f;
            unsigned skipmask = 0;
            const float4* row = c2 + i * (OO / 4) + lane;
#pragma unroll
            for (int k = 0; k < 8; ++k) {
                const float4 v = __ldg(row + k * 32);
                const float mn = fminf(fminf(v.x, v.y), fminf(v.z, v.w));
                if (__any_sync(0xffffffffu, mn <= tb.w)) {
#define AEG_DO(comp, slot, pacc) {                                                  \
                    float x_ = fmaf(comp, tb.y, EPSV);                              \
                    float s_; asm("rsqrt.approx.ftz.f32 %0, %1;" : "=f"(s_) : "f"(x_)); \
                    float a_ = fmaf(s_, L2E, tb.z);                                 \
                    float e_; asm("ex2.approx.ftz.f32 %0, %1;" : "=f"(e_) : "f"(a_)); \
                    e[slot] = e_; pacc += e_; }
                    AEG_DO(v.x, k * 4 + 0, p0)
                    AEG_DO(v.y, k * 4 + 1, p1)
                    AEG_DO(v.z, k * 4 + 2, p2)
                    AEG_DO(v.w, k * 4 + 3, p3)
#undef AEG_DO
                } else {
                    skipmask |= (1u << k);
                }
            }
            float ps = (p0 + p1) + (p2 + p3);
#pragma unroll
            for (int off = 16; off > 0; off >>= 1)
                ps += __shfl_xor_sync(0xffffffffu, ps, off);
            const float gz = __fdividef(tb.x, ps);
#pragma unroll
            for (int k = 0; k < 8; ++k) {
                if (!(skipmask & (1u << k))) {
#pragma unroll
                    for (int j = 0; j < 4; ++j) {
                        const float val = gz * e[k * 4 + j];
                        if (fabsf(val) > 1e-18f)
                            atomicAdd(outb + k * 128 + lane * 4 + j, val);
                    }
                }
            }
        }
    }
}

extern "C" void kernel_launch(void* const* d_in, const int* in_sizes, int n_in,
                              void* d_out, int out_size) {
    (void)in_sizes; (void)n_in; (void)out_size;
    const float* data = (const float*)d_in[0];
    const float* ix   = (const float*)d_in[1];
    const float* iy   = (const float*)d_in[2];
    const float* ox   = (const float*)d_in[3];
    const float* oy   = (const float*)d_in[4];
    const float* la   = (const float*)d_in[5];
    const float* lm   = (const float*)d_in[6];
    float* out = (float*)d_out;

    init_kernel<<<(BB * OO) / 1024, 1024>>>(out);
    prep_kernel<<<dim3(NI / 32, OO / 32), dim3(32, 8)>>>(ix, iy, ox, oy, la, lm);
    cand_kernel<<<NI, 256>>>();
    tab_kernel<<<(BB * NI) / 256, 256>>>(data);
    main_kernel<<<dim3(BB / BW, NCHUNK), 128>>>(out);
}

// round 10
// speedup vs baseline: 3.3047x; 2.1508x over previous
#include <cuda_runtime.h>
#include <cuda_bf16.h>
#include <math_constants.h>

// Problem: B=128, O=1024, I=1024
//   c[o,i]   = (ix/iy + la)*(1+lm) - ox/oy               (batch independent)
//   s[b,o,i] = rsqrt(c^2 * sigmoid(d[b,i])^2 + eps)
//   w        = softmax over o of s ; out[b,o] = sum_i d[b,i]*w
//
// R7: 3-kernel pipeline.
//   prep: c^2 transposed to [i][o] (+ zeroes out)
//   cand: per row i: min (pass1) -> trow -> candidate compact (pass2), n<=8
//   main: per (b,i): inline sigmoid/m/T; fast path = 8 lanes per (b,i)
//         (4 pairs per warp-step, 3-shfl Z reduce, ~2 atomicAdds);
//         exact check T_b <= trow falls back to full-row two-pass.

#define BB 128
#define OO 1024
#define NI 1024
#define NCHUNK 32
#define ICH (NI / NCHUNK)   // 32 i per warp
#define BW 4                // warps (= batches) per block
#define EPSV 1e-7f
#define L2E 1.4426950408889634f
#define MC 8                // fast-tier candidate capacity

__device__ float  g_c2T[NI * OO];        // c^2, [i][o] layout (4 MB)
__device__ float4 g_rowinfo[NI];         // {cmin, trow, n (int bits), 0}
__device__ float  g_candv[NI * MC];      // candidate c^2, +inf padded
__device__ int    g_cando[NI * MC];      // candidate o

__global__ __launch_bounds__(256) void prep_kernel(
    const float* __restrict__ ix, const float* __restrict__ iy,
    const float* __restrict__ ox, const float* __restrict__ oy,
    const float* __restrict__ la, const float* __restrict__ lm,
    float* __restrict__ out)
{
    __shared__ float tile[32][33];
    const int i0 = blockIdx.x * 32;
    const int o0 = blockIdx.y * 32;
    const int tx = threadIdx.x;
    const int ty = threadIdx.y;

    // fold output zeroing in (atomics accumulate into out later)
    {
        const int bid = blockIdx.y * gridDim.x + blockIdx.x;     // 0..1023
        const int t = ty * 32 + tx;                              // 0..255
        if (t < 128) out[bid * 128 + t] = 0.0f;                  // 1024*128 = BB*OO
    }

#pragma unroll
    for (int r = 0; r < 4; ++r) {
        const int ol = ty + r * 8;
        const int idx = (o0 + ol) * NI + i0 + tx;
        const float inp = ix[idx] / iy[idx];     // IEEE div: c is cancellation-sensitive
        const float ou  = ox[idx] / oy[idx];
        const float c   = (inp + la[idx]) * (1.0f + lm[idx]) - ou;
        tile[ol][tx] = c * c;
    }
    __syncthreads();

#pragma unroll
    for (int r = 0; r < 4; ++r) {
        const int il = ty + r * 8;
        g_c2T[(i0 + il) * OO + o0 + tx] = tile[tx][il];   // coalesced in o
    }
}

// One warp per row i: pass1 min -> trow; pass2 compact candidates (c^2 <= trow).
__global__ __launch_bounds__(256) void cand_kernel() {
    const int warp = threadIdx.x >> 5;
    const int lane = threadIdx.x & 31;
    const int i = blockIdx.x * 8 + warp;
    __shared__ int cnt[8];

    const float4* row = reinterpret_cast<const float4*>(g_c2T) + i * (OO / 4) + lane;
    float4 v[8];
    float mn = CUDART_INF_F;
#pragma unroll
    for (int k = 0; k < 8; ++k) {
        v[k] = __ldg(row + k * 32);
        mn = fminf(mn, fminf(fminf(v[k].x, v[k].y), fminf(v[k].z, v[k].w)));
    }
#pragma unroll
    for (int off = 16; off > 0; off >>= 1)
        mn = fminf(mn, __shfl_xor_sync(0xffffffffu, mn, off));   // all lanes hold row min

    float m1;                                    // smallest possible softmax max over b
    asm("rsqrt.approx.ftz.f32 %0, %1;" : "=f"(m1) : "f"(mn + EPSV));
    float trow;
    if (m1 > 28.0f) {
        const float t = __fdividef(1.0f, m1 - 26.0f);            // margin 26 vs T_b's 25
        trow = fmaf(t, t, 2e-5f);                                // eps-term cover, sig2 >= ~1e-4
    } else {
        trow = CUDART_INF_F;                     // weak peaking: slow path (n sentinel below)
    }

    if (lane == 0) cnt[warp] = 0;
    if (lane < MC) {                             // +inf pad: rsqrt->0, e ~ 2^-40, masked anyway
        g_candv[i * MC + lane] = CUDART_INF_F;
        g_cando[i * MC + lane] = 0;
    }
    __syncwarp();

#pragma unroll
    for (int k = 0; k < 8; ++k) {
#define CAND_DO(comp, j) if (comp <= trow) {                                   \
            const int p = atomicAdd(&cnt[warp], 1);                            \
            if (p < MC) { g_candv[i * MC + p] = comp;                          \
                          g_cando[i * MC + p] = k * 128 + lane * 4 + j; } }
        CAND_DO(v[k].x, 0) CAND_DO(v[k].y, 1) CAND_DO(v[k].z, 2) CAND_DO(v[k].w, 3)
#undef CAND_DO
    }
    __syncwarp();
    if (lane == 0) {
        const int n = cnt[warp];
        g_rowinfo[i] = make_float4(mn, trow, __int_as_float(n > MC ? OO + 1 : n), 0.0f);
    }
}

__global__ __launch_bounds__(128, 8) void main_kernel(const float* __restrict__ dptr,
                                                      float* __restrict__ out) {
    const unsigned FULL = 0xffffffffu;
    const int lane = threadIdx.x & 31;
    const int warp = threadIdx.x >> 5;
    const int grp  = lane >> 3;                  // 4 groups of 8 lanes: 4 (b,i) per step
    const int gl   = lane & 7;
    const int b    = blockIdx.x * BW + warp;     // one batch per warp
    const int i0   = blockIdx.y * ICH;
    float* const outb = out + b * OO;

    for (int step = 0; step < ICH / 4; ++step) {
        const int i = i0 + step * 4 + grp;
        const float dv = __ldg(dptr + b * NI + i);

        // --- inline per-(b,i) table: sigmoid^2, softmax max m, skip threshold T ---
        float ex_;
        asm("ex2.approx.ftz.f32 %0, %1;" : "=f"(ex_) : "f"(-dv * L2E));
        const float sig  = __fdividef(1.0f, 1.0f + ex_);
        const float sig2 = sig * sig;

        const float4 ri = g_rowinfo[i];          // {cmin, trow, n, _}: 4 consec i -> 64B
        const float trow = ri.y;
        const int   n    = __float_as_int(ri.z);

        float m_;
        asm("rsqrt.approx.ftz.f32 %0, %1;" : "=f"(m_) : "f"(fmaf(ri.x, sig2, EPSV)));
        const float nmL = -(m_ * L2E);

        float T;                                 // s >= m-25  <=>  c^2 <= T
        if (m_ > 27.0f) {
            const float t = __fdividef(1.0f, m_ - 25.0f);
            T = fmaf(t, t, -EPSV) * __fdividef(1.0f, sig2);
        } else {
            T = CUDART_INF_F;
        }

        const bool ok = (T <= trow) && (n <= MC);        // group-uniform
        const unsigned okm = __ballot_sync(FULL, ok);

        if (ok) {
            // ---- fast path: 8 lanes cover all candidates of (b,i) ----
            const float c2v = __ldg(g_candv + i * MC + gl);   // 4 consec i -> 128B wavefront
            const int   oo  = __ldg(g_cando + i * MC + gl);
            float s_, e_;
            asm("rsqrt.approx.ftz.f32 %0, %1;" : "=f"(s_) : "f"(fmaf(c2v, sig2, EPSV)));
            asm("ex2.approx.ftz.f32 %0, %1;"   : "=f"(e_) : "f"(fmaf(s_, L2E, nmL)));
            float ps = e_;                       // Z: argmin lane reproduces e == 1 exactly
            ps += __shfl_xor_sync(okm, ps, 1);
            ps += __shfl_xor_sync(okm, ps, 2);
            ps += __shfl_xor_sync(okm, ps, 4);
            const float val = __fdividef(dv, ps) * e_;
            if (gl < n && fabsf(val) > 1e-18f)
                atomicAdd(outb + oo, val);
        }

        if (okm != FULL) {
            // ---- slow path: full row, whole warp, two-pass (rare) ----
#pragma unroll 1
            for (int g2 = 0; g2 < 4; ++g2) {
                if ((okm >> (g2 * 8)) & 1u) continue;
                const float dvg = __shfl_sync(FULL, dv,   g2 * 8);
                const float s2g = __shfl_sync(FULL, sig2, g2 * 8);
                const float nmg = __shfl_sync(FULL, nmL,  g2 * 8);
                const float Tg  = __shfl_sync(FULL, T,    g2 * 8);
                const int   ig  = i0 + step * 4 + g2;
                const float4* row = reinterpret_cast<const float4*>(g_c2T)
                                    + ig * (OO / 4) + lane;
                unsigned skip = 0;
                float p = 0.0f;
#pragma unroll
                for (int k = 0; k < 8; ++k) {
                    const float4 v = __ldg(row + k * 32);
                    const float mn = fminf(fminf(v.x, v.y), fminf(v.z, v.w));
                    if (__any_sync(FULL, mn <= Tg)) {
#define AEG_Z(comp) { float x_ = fmaf(comp, s2g, EPSV);                          \
                      float s_; asm("rsqrt.approx.ftz.f32 %0, %1;" : "=f"(s_) : "f"(x_)); \
                      float e_; asm("ex2.approx.ftz.f32 %0, %1;" : "=f"(e_)       \
                                    : "f"(fmaf(s_, L2E, nmg)));                   \
                      p += e_; }
                        AEG_Z(v.x) AEG_Z(v.y) AEG_Z(v.z) AEG_Z(v.w)
#undef AEG_Z
                    } else skip |= (1u << k);
                }
#pragma unroll
                for (int off = 16; off > 0; off >>= 1)
                    p += __shfl_xor_sync(FULL, p, off);
                const float gz = __fdividef(dvg, p);
#pragma unroll
                for (int k = 0; k < 8; ++k) {
                    if (skip & (1u << k)) continue;
                    const float4 v = __ldg(row + k * 32);    // L1-hot reload
#define AEG_W(comp, j) { float x_ = fmaf(comp, s2g, EPSV);                       \
                      float s_; asm("rsqrt.approx.ftz.f32 %0, %1;" : "=f"(s_) : "f"(x_)); \
                      float e_; asm("ex2.approx.ftz.f32 %0, %1;" : "=f"(e_)       \
                                    : "f"(fmaf(s_, L2E, nmg)));                   \
                      const float val = gz * e_;                                  \
                      if (fabsf(val) > 1e-18f)                                    \
                          atomicAdd(outb + k * 128 + lane * 4 + j, val); }
                    AEG_W(v.x, 0) AEG_W(v.y, 1) AEG_W(v.z, 2) AEG_W(v.w, 3)
#undef AEG_W
                }
            }
        }
    }
}

extern "C" void kernel_launch(void* const* d_in, const int* in_sizes, int n_in,
                              void* d_out, int out_size) {
    (void)in_sizes; (void)n_in; (void)out_size;
    const float* data = (const float*)d_in[0];
    const float* ix   = (const float*)d_in[1];
    const float* iy   = (const float*)d_in[2];
    const float* ox   = (const float*)d_in[3];
    const float* oy   = (const float*)d_in[4];
    const float* la   = (const float*)d_in[5];
    const float* lm   = (const float*)d_in[6];
    float* out = (float*)d_out;

    prep_kernel<<<dim3(NI / 32, OO / 32), dim3(32, 8)>>>(ix, iy, ox, oy, la, lm, out);
    cand_kernel<<<NI / 8, 256>>>();
    main_kernel<<<dim3(BB / BW, NCHUNK), 128>>>(data, out);
}

// round 14
// speedup vs baseline: 3.3450x; 1.0122x over previous
#include <cuda_runtime.h>
#include <cuda_bf16.h>
#include <math_constants.h>

// Problem: B=128, O=1024, I=1024
//   c[o,i]   = (ix/iy + la)*(1+lm) - ox/oy               (batch independent)
//   s[b,o,i] = rsqrt(c^2 * sigmoid(d[b,i])^2 + eps)
//   w        = softmax over o of s ; out[b,o] = sum_i d[b,i]*w
//
// R12: R11 prep (MLP-batched loads + smem transpose) with the misaligned
// STS.128 fixed: tile rows are 129 floats (516B) so float4 smem stores trap
// for odd rows; store 4 scalars instead (4-way bank conflict, hidden under
// the DRAM-latency-bound load stream; the 129 stride keeps transpose READS
// conflict-free). cand/main unchanged from the 21.2us R10 kernel.

#define BB 128
#define OO 1024
#define NI 1024
#define NCHUNK 32
#define ICH (NI / NCHUNK)   // 32 i per warp
#define BW 4                // warps (= batches) per block
#define EPSV 1e-7f
#define L2E 1.4426950408889634f
#define MC 8                // fast-tier candidate capacity

__device__ float  g_c2T[NI * OO];        // c^2, [i][o] layout (4 MB)
__device__ float4 g_rowinfo[NI];         // {cmin, trow, n (int bits), 0}
__device__ float  g_candv[NI * MC];      // candidate c^2, +inf padded
__device__ int    g_cando[NI * MC];      // candidate o

__global__ __launch_bounds__(256) void prep_kernel(
    const float* __restrict__ ix, const float* __restrict__ iy,
    const float* __restrict__ ox, const float* __restrict__ oy,
    const float* __restrict__ la, const float* __restrict__ lm,
    float* __restrict__ out)
{
    __shared__ float tile[32][129];          // [o_local][i_local]; +1 pad: transpose reads conflict-free
    const int i0 = blockIdx.x * 128;
    const int o0 = blockIdx.y * 32;
    const int t  = threadIdx.x;
    const int tx = t & 31;                   // float4 column within the 128-i tile
    const int ty = t >> 5;                   // warp id = o-row group (0..7)

    // fold output zeroing in: 256 blocks x 512 floats = BB*OO
    {
        const int bid = blockIdx.y * gridDim.x + blockIdx.x;      // 0..255
        reinterpret_cast<float2*>(out)[bid * 256 + t] = make_float2(0.0f, 0.0f);
    }

#pragma unroll
    for (int h = 0; h < 2; ++h) {
        float4 vix[2], viy[2], vox[2], voy[2], vla[2], vlm[2];
#pragma unroll
        for (int r = 0; r < 2; ++r) {        // 12 LDG.128 batched -> MLP 12/thread
            const int ol = (h * 2 + r) * 8 + ty;
            const int base = (o0 + ol) * NI + i0 + tx * 4;
            vix[r] = *reinterpret_cast<const float4*>(ix + base);
            viy[r] = *reinterpret_cast<const float4*>(iy + base);
            vox[r] = *reinterpret_cast<const float4*>(ox + base);
            voy[r] = *reinterpret_cast<const float4*>(oy + base);
            vla[r] = *reinterpret_cast<const float4*>(la + base);
            vlm[r] = *reinterpret_cast<const float4*>(lm + base);
        }
#pragma unroll
        for (int r = 0; r < 2; ++r) {
            const int ol = (h * 2 + r) * 8 + ty;
            // IEEE div: c is cancellation-sensitive (matches ref exactly)
            const float cx = (vix[r].x / viy[r].x + vla[r].x) * (1.0f + vlm[r].x) - vox[r].x / voy[r].x;
            const float cy = (vix[r].y / viy[r].y + vla[r].y) * (1.0f + vlm[r].y) - vox[r].y / voy[r].y;
            const float cz = (vix[r].z / viy[r].z + vla[r].z) * (1.0f + vlm[r].z) - vox[r].z / voy[r].z;
            const float cw = (vix[r].w / viy[r].w + vla[r].w) * (1.0f + vlm[r].w) - vox[r].w / voy[r].w;
            // scalar STS.32: 516B row stride means float4 stores would be
            // misaligned for odd ol (HW trap). 4-way bank conflict here is
            // hidden under the DRAM-latency-bound loads above.
            tile[ol][tx * 4 + 0] = cx * cx;
            tile[ol][tx * 4 + 1] = cy * cy;
            tile[ol][tx * 4 + 2] = cz * cz;
            tile[ol][tx * 4 + 3] = cw * cw;
        }
    }
    __syncthreads();

    // transpose out: warp ty writes i-rows [ty*16, ty*16+16), 128B coalesced in o
#pragma unroll
    for (int k = 0; k < 16; ++k) {
        const int ii = ty * 16 + k;
        g_c2T[(i0 + ii) * OO + o0 + tx] = tile[tx][ii];           // LDS bank (tx+ii)%32: conflict-free
    }
}

// One warp per row i: pass1 min -> trow; pass2 compact candidates (c^2 <= trow).
__global__ __launch_bounds__(256) void cand_kernel() {
    const int warp = threadIdx.x >> 5;
    const int lane = threadIdx.x & 31;
    const int i = blockIdx.x * 8 + warp;
    __shared__ int cnt[8];

    const float4* row = reinterpret_cast<const float4*>(g_c2T) + i * (OO / 4) + lane;
    float4 v[8];
    float mn = CUDART_INF_F;
#pragma unroll
    for (int k = 0; k < 8; ++k) {
        v[k] = __ldg(row + k * 32);
        mn = fminf(mn, fminf(fminf(v[k].x, v[k].y), fminf(v[k].z, v[k].w)));
    }
#pragma unroll
    for (int off = 16; off > 0; off >>= 1)
        mn = fminf(mn, __shfl_xor_sync(0xffffffffu, mn, off));   // all lanes hold row min

    float m1;                                    // smallest possible softmax max over b
    asm("rsqrt.approx.ftz.f32 %0, %1;" : "=f"(m1) : "f"(mn + EPSV));
    float trow;
    if (m1 > 28.0f) {
        const float t = __fdividef(1.0f, m1 - 26.0f);            // margin 26 vs T_b's 25
        trow = fmaf(t, t, 2e-5f);                                // eps-term cover, sig2 >= ~1e-4
    } else {
        trow = CUDART_INF_F;                     // weak peaking: slow path (n sentinel below)
    }

    if (lane == 0) cnt[warp] = 0;
    if (lane < MC) {                             // +inf pad: rsqrt->0, e ~ 2^-40, masked anyway
        g_candv[i * MC + lane] = CUDART_INF_F;
        g_cando[i * MC + lane] = 0;
    }
    __syncwarp();

#pragma unroll
    for (int k = 0; k < 8; ++k) {
#define CAND_DO(comp, j) if (comp <= trow) {                                   \
            const int p = atomicAdd(&cnt[warp], 1);                            \
            if (p < MC) { g_candv[i * MC + p] = comp;                          \
                          g_cando[i * MC + p] = k * 128 + lane * 4 + j; } }
        CAND_DO(v[k].x, 0) CAND_DO(v[k].y, 1) CAND_DO(v[k].z, 2) CAND_DO(v[k].w, 3)
#undef CAND_DO
    }
    __syncwarp();
    if (lane == 0) {
        const int n = cnt[warp];
        g_rowinfo[i] = make_float4(mn, trow, __int_as_float(n > MC ? OO + 1 : n), 0.0f);
    }
}

__global__ __launch_bounds__(128, 8) void main_kernel(const float* __restrict__ dptr,
                                                      float* __restrict__ out) {
    const unsigned FULL = 0xffffffffu;
    const int lane = threadIdx.x & 31;
    const int warp = threadIdx.x >> 5;
    const int grp  = lane >> 3;                  // 4 groups of 8 lanes: 4 (b,i) per step
    const int gl   = lane & 7;
    const int b    = blockIdx.x * BW + warp;     // one batch per warp
    const int i0   = blockIdx.y * ICH;
    float* const outb = out + b * OO;

    for (int step = 0; step < ICH / 4; ++step) {
        const int i = i0 + step * 4 + grp;
        const float dv = __ldg(dptr + b * NI + i);

        // --- inline per-(b,i) table: sigmoid^2, softmax max m, skip threshold T ---
        float ex_;
        asm("ex2.approx.ftz.f32 %0, %1;" : "=f"(ex_) : "f"(-dv * L2E));
        const float sig  = __fdividef(1.0f, 1.0f + ex_);
        const float sig2 = sig * sig;

        const float4 ri = g_rowinfo[i];          // {cmin, trow, n, _}: 4 consec i -> 64B
        const float trow = ri.y;
        const int   n    = __float_as_int(ri.z);

        float m_;
        asm("rsqrt.approx.ftz.f32 %0, %1;" : "=f"(m_) : "f"(fmaf(ri.x, sig2, EPSV)));
        const float nmL = -(m_ * L2E);

        float T;                                 // s >= m-25  <=>  c^2 <= T
        if (m_ > 27.0f) {
            const float t = __fdividef(1.0f, m_ - 25.0f);
            T = fmaf(t, t, -EPSV) * __fdividef(1.0f, sig2);
        } else {
            T = CUDART_INF_F;
        }

        const bool ok = (T <= trow) && (n <= MC);        // group-uniform
        const unsigned okm = __ballot_sync(FULL, ok);

        if (ok) {
            // ---- fast path: 8 lanes cover all candidates of (b,i) ----
            const float c2v = __ldg(g_candv + i * MC + gl);   // 4 consec i -> 128B wavefront
            const int   oo  = __ldg(g_cando + i * MC + gl);
            float s_, e_;
            asm("rsqrt.approx.ftz.f32 %0, %1;" : "=f"(s_) : "f"(fmaf(c2v, sig2, EPSV)));
            asm("ex2.approx.ftz.f32 %0, %1;"   : "=f"(e_) : "f"(fmaf(s_, L2E, nmL)));
            float ps = e_;                       // Z: argmin lane reproduces e == 1 exactly
            ps += __shfl_xor_sync(okm, ps, 1);
            ps += __shfl_xor_sync(okm, ps, 2);
            ps += __shfl_xor_sync(okm, ps, 4);
            const float val = __fdividef(dv, ps) * e_;
            if (gl < n && fabsf(val) > 1e-18f)
                atomicAdd(outb + oo, val);
        }

        if (okm != FULL) {
            // ---- slow path: full row, whole warp, two-pass (rare) ----
#pragma unroll 1
            for (int g2 = 0; g2 < 4; ++g2) {
                if ((okm >> (g2 * 8)) & 1u) continue;
                const float dvg = __shfl_sync(FULL, dv,   g2 * 8);
                const float s2g = __shfl_sync(FULL, sig2, g2 * 8);
                const float nmg = __shfl_sync(FULL, nmL,  g2 * 8);
                const float Tg  = __shfl_sync(FULL, T,    g2 * 8);
                const int   ig  = i0 + step * 4 + g2;
                const float4* row = reinterpret_cast<const float4*>(g_c2T)
                                    + ig * (OO / 4) + lane;
                unsigned skip = 0;
                float p = 0.0f;
#pragma unroll
                for (int k = 0; k < 8; ++k) {
                    const float4 v = __ldg(row + k * 32);
                    const float mn = fminf(fminf(v.x, v.y), fminf(v.z, v.w));
                    if (__any_sync(FULL, mn <= Tg)) {
#define AEG_Z(comp) { float x_ = fmaf(comp, s2g, EPSV);                          \
                      float s_; asm("rsqrt.approx.ftz.f32 %0, %1;" : "=f"(s_) : "f"(x_)); \
                      float e_; asm("ex2.approx.ftz.f32 %0, %1;" : "=f"(e_)       \
                                    : "f"(fmaf(s_, L2E, nmg)));                   \
                      p += e_; }
                        AEG_Z(v.x) AEG_Z(v.y) AEG_Z(v.z) AEG_Z(v.w)
#undef AEG_Z
                    } else skip |= (1u << k);
                }
#pragma unroll
                for (int off = 16; off > 0; off >>= 1)
                    p += __shfl_xor_sync(FULL, p, off);
                const float gz = __fdividef(dvg, p);
#pragma unroll
                for (int k = 0; k < 8; ++k) {
                    if (skip & (1u << k)) continue;
                    const float4 v = __ldg(row + k * 32);    // L1-hot reload
#define AEG_W(comp, j) { float x_ = fmaf(comp, s2g, EPSV);                       \
                      float s_; asm("rsqrt.approx.ftz.f32 %0, %1;" : "=f"(s_) : "f"(x_)); \
                      float e_; asm("ex2.approx.ftz.f32 %0, %1;" : "=f"(e_)       \
                                    : "f"(fmaf(s_, L2E, nmg)));                   \
                      const float val = gz * e_;                                  \
                      if (fabsf(val) > 1e-18f)                                    \
                          atomicAdd(outb + k * 128 + lane * 4 + j, val); }
                    AEG_W(v.x, 0) AEG_W(v.y, 1) AEG_W(v.z, 2) AEG_W(v.w, 3)
#undef AEG_W
                }
            }
        }
    }
}

extern "C" void kernel_launch(void* const* d_in, const int* in_sizes, int n_in,
                              void* d_out, int out_size) {
    (void)in_sizes; (void)n_in; (void)out_size;
    const float* data = (const float*)d_in[0];
    const float* ix   = (const float*)d_in[1];
    const float* iy   = (const float*)d_in[2];
    const float* ox   = (const float*)d_in[3];
    const float* oy   = (const float*)d_in[4];
    const float* la   = (const float*)d_in[5];
    const float* lm   = (const float*)d_in[6];
    float* out = (float*)d_out;

    prep_kernel<<<dim3(NI / 128, OO / 32), 256>>>(ix, iy, ox, oy, la, lm, out);
    cand_kernel<<<NI / 8, 256>>>();
    main_kernel<<<dim3(BB / BW, NCHUNK), 128>>>(data, out);
}